// round 4
// baseline (speedup 1.0000x reference)
#include <cuda_runtime.h>
#include <math.h>

#define Bb 64
#define Tt 128
#define Ii 1024
#define Hh 4096
#define NNZ_IH 262144
#define NNZ_HH 1048576
#define HB (Hh * Bb)

#define NW_HH 8              // col windows of 512 for hh
#define NW_IH 2              // col windows of 512 for ih
#define WINC 512
#define NK_HH (NW_HH * Hh)   // 32768 buckets
#define NK_IH (NW_IH * Hh)   // 8192 buckets
#define PAD_HH (NNZ_HH + 8 * NK_HH)   // 1310720
#define PAD_IH (NNZ_IH + 8 * NK_IH)   // 327680
#define NC 16                // row chunks of 256

// ---------------- device scratch ----------------
__device__ float g_xT[Tt * Ii * Bb];        // (T, I, B)  32MB
__device__ float g_ihb[Tt * Hh * Bb];       // ih preact per t  128MB
__device__ float g_h[HB];                   // hidden (H, B)
__device__ float g_hact[HB];                // tanh(pre)
__device__ float g_part[NW_HH * HB];        // hh window partials  8MB

__device__ int   g_hh_bptr[NK_HH + 1];
__device__ int   g_hh_bcnt[NK_HH];
__device__ int2  g_hh_pair[PAD_HH];         // {local byte offset, val bits}

__device__ int   g_ih_bptr[NK_IH + 1];
__device__ int   g_ih_bcnt[NK_IH];
__device__ int2  g_ih_pair[PAD_IH];

__device__ int   g_bsum[64];                // scan block sums

// ---------------- prep ----------------

__global__ void k_zero_all() {
    int i = blockIdx.x * blockDim.x + threadIdx.x;    // 262144 threads
    if (i < NK_HH) g_hh_bcnt[i] = 0;
    if (i < NK_IH) g_ih_bcnt[i] = 0;
    if (i < HB) g_h[i] = 0.f;
}

__global__ void k_zero_pairs() {
    int4 z; z.x = z.y = z.z = z.w = 0;
    int n1 = PAD_HH / 2, n2 = PAD_IH / 2;     // int4 units
    for (int i = blockIdx.x * blockDim.x + threadIdx.x; i < n1 + n2;
         i += gridDim.x * blockDim.x) {
        if (i < n1) ((int4*)g_hh_pair)[i] = z;
        else        ((int4*)g_ih_pair)[i - n1] = z;
    }
}

__global__ void k_hist(const int* __restrict__ rows, const int* __restrict__ cols,
                       int n, int which) {
    int* cnt = (which == 0) ? g_hh_bcnt : g_ih_bcnt;
    for (int i = blockIdx.x * blockDim.x + threadIdx.x; i < n;
         i += gridDim.x * blockDim.x) {
        int key = (cols[i] >> 9) * Hh + rows[i];
        atomicAdd(&cnt[key], 1);
    }
}

// ---- 3-phase exclusive scan of padded counts ----
__global__ void k_scan_p1(int which, int n) {
    const int* cnt = (which == 0) ? g_hh_bcnt : g_ih_bcnt;
    __shared__ int sw[32];
    int tid = threadIdx.x;
    int i = blockIdx.x * 1024 + tid;
    int v = (i < n) ? ((cnt[i] + 7) & ~7) : 0;
    int s = v;
    #pragma unroll
    for (int o = 16; o > 0; o >>= 1) s += __shfl_down_sync(0xffffffffu, s, o);
    if ((tid & 31) == 0) sw[tid >> 5] = s;
    __syncthreads();
    if (tid < 32) {
        s = sw[tid];
        #pragma unroll
        for (int o = 16; o > 0; o >>= 1) s += __shfl_down_sync(0xffffffffu, s, o);
        if (tid == 0) g_bsum[blockIdx.x] = s;
    }
}

__global__ void k_scan_p2(int nb) {      // single warp
    int tid = threadIdx.x;
    int v = (tid < nb) ? g_bsum[tid] : 0;
    int incl = v;
    #pragma unroll
    for (int o = 1; o < 32; o <<= 1) {
        int u = __shfl_up_sync(0xffffffffu, incl, o);
        if (tid >= o) incl += u;
    }
    if (tid < nb) g_bsum[tid] = incl - v;
    if (tid == 31) g_bsum[nb] = incl;    // grand total
}

__global__ void k_scan_p3(int which, int n, int nb) {
    int* cnt = (which == 0) ? g_hh_bcnt : g_ih_bcnt;
    int* ptr = (which == 0) ? g_hh_bptr : g_ih_bptr;
    __shared__ int part[1024];
    int tid = threadIdx.x;
    int i = blockIdx.x * 1024 + tid;
    int v = (i < n) ? ((cnt[i] + 7) & ~7) : 0;
    part[tid] = v;
    __syncthreads();
    for (int o = 1; o < 1024; o <<= 1) {
        int u = (tid >= o) ? part[tid - o] : 0;
        __syncthreads();
        part[tid] += u;
        __syncthreads();
    }
    if (i < n) {
        int excl = part[tid] - v + g_bsum[blockIdx.x];
        ptr[i] = excl;
        cnt[i] = excl;       // scatter cursor
        if (i == n - 1) ptr[n] = g_bsum[nb];
    }
}

// scatter into padded bucket arrays; offsets local to 512-col window
__global__ void k_scatter(const int* __restrict__ rows, const int* __restrict__ cols,
                          const float* __restrict__ vals, int n, int which) {
    int* cur = (which == 0) ? g_hh_bcnt : g_ih_bcnt;
    int2* pair = (which == 0) ? g_hh_pair : g_ih_pair;
    for (int i = blockIdx.x * blockDim.x + threadIdx.x; i < n;
         i += gridDim.x * blockDim.x) {
        int c = cols[i];
        int key = (c >> 9) * Hh + rows[i];
        int p = atomicAdd(&cur[key], 1);
        int2 pr;
        pr.x = (c & (WINC - 1)) * (Bb * 4);
        pr.y = __float_as_int(vals[i]);
        pair[p] = pr;
    }
}

// transpose x (B,T,I) -> g_xT (T,I,B)
__global__ void k_transpose(const float* __restrict__ x) {
    __shared__ float tile[32][Bb + 1];
    int i0 = blockIdx.x * 32;
    int t = blockIdx.y;
    int tx = threadIdx.x, ty = threadIdx.y;    // block (32, 8)
    #pragma unroll
    for (int bq = 0; bq < 8; bq++) {
        int b = ty + 8 * bq;
        tile[tx][b] = x[((size_t)b * Tt + t) * Ii + i0 + tx];
    }
    __syncthreads();
    int lin = ty * 32 + tx;
    #pragma unroll
    for (int k = 0; k < 8; k++) {
        int idx = lin + 256 * k;
        int iy = idx >> 6;
        int b = idx & 63;
        g_xT[((size_t)t * Ii + i0 + iy) * Bb + b] = tile[iy][b];
    }
}

// ---------------- gather core (padded buckets of 8) ----------------
__device__ __forceinline__ void bucket8(const int2* __restrict__ pair, int s, int e,
                                        const char* shb, int lane8,
                                        float& ax, float& ay) {
    for (int base = s; base < e; base += 8) {
        int2 q[8];
        #pragma unroll
        for (int j = 0; j < 8; j++) q[j] = __ldg(&pair[base + j]);
        #pragma unroll
        for (int j = 0; j < 8; j++) {
            float2 hv = *(const float2*)(shb + q[j].x + lane8);
            float v = __int_as_float(q[j].y);
            ax = fmaf(v, hv.x, ax);
            ay = fmaf(v, hv.y, ay);
        }
    }
}

// ---------------- ih precompute: grid (NC, Tt), windowed smem ----------------
__global__ void __launch_bounds__(1024, 1) k_ih() {
    extern __shared__ float sh[];
    int t = blockIdx.y;
    int chunk0 = blockIdx.x * 256;
    int tid = threadIdx.x;
    int lane = tid & 31, warp = tid >> 5;
    int lane8 = lane << 3;
    const char* shb = (const char*)sh;
    float2 acc[8];
    #pragma unroll
    for (int k = 0; k < 8; k++) { acc[k].x = 0.f; acc[k].y = 0.f; }

    for (int w = 0; w < NW_IH; w++) {
        __syncthreads();
        {
            const float4* src = (const float4*)(g_xT + (size_t)t * Ii * Bb + w * WINC * Bb);
            float4* dst = (float4*)sh;
            #pragma unroll
            for (int i = tid; i < WINC * Bb / 4; i += 1024) dst[i] = src[i];
        }
        __syncthreads();
        #pragma unroll
        for (int k = 0; k < 8; k++) {
            int r = chunk0 + warp + 32 * k;
            int s = g_ih_bptr[w * Hh + r];
            int e = g_ih_bptr[w * Hh + r + 1];
            bucket8(g_ih_pair, s, e, shb, lane8, acc[k].x, acc[k].y);
        }
    }
    float* ob = g_ihb + (size_t)t * HB;
    #pragma unroll
    for (int k = 0; k < 8; k++) {
        int r = chunk0 + warp + 32 * k;
        ((float2*)(ob + r * Bb))[lane] = acc[k];
    }
}

// ---------------- per-step kernels ----------------

// hh windowed spmm: grid (NC, NW_HH), 1024 threads, 128KB smem
__global__ void __launch_bounds__(1024, 1) k_hh() {
    extern __shared__ float sh[];
    int w = blockIdx.y;
    int chunk0 = blockIdx.x * 256;
    int tid = threadIdx.x;
    {
        const float4* src = (const float4*)(g_h + w * WINC * Bb);
        float4* dst = (float4*)sh;
        #pragma unroll
        for (int i = tid; i < WINC * Bb / 4; i += 1024) dst[i] = src[i];
    }
    __syncthreads();
    int lane = tid & 31, warp = tid >> 5;
    int lane8 = lane << 3;
    const char* shb = (const char*)sh;
    #pragma unroll
    for (int k = 0; k < 8; k++) {
        int r = chunk0 + warp + 32 * k;
        int s = g_hh_bptr[w * Hh + r];
        int e = g_hh_bptr[w * Hh + r + 1];
        float ax = 0.f, ay = 0.f;
        bucket8(g_hh_pair, s, e, shb, lane8, ax, ay);
        float2 o; o.x = ax; o.y = ay;
        ((float2*)(g_part + (size_t)(w * Hh + r) * Bb))[lane] = o;
    }
}

// pre = biases + ihb[t] + sum_w part[w]; hact = tanh(pre)
__global__ void __launch_bounds__(1024) k_reduce(int t, const float* __restrict__ b_ih,
                                                 const float* __restrict__ b_hh) {
    int idx = blockIdx.x * blockDim.x + threadIdx.x;    // over HB
    int r = idx >> 6;
    float s = b_ih[r] + b_hh[r] + g_ihb[(size_t)t * HB + idx];
    #pragma unroll
    for (int w = 0; w < NW_HH; w++) s += g_part[(size_t)w * HB + idx];
    g_hact[idx] = tanhf(s);
}

// layernorm over H for one batch column + write h and out[b][t][:]
__global__ void __launch_bounds__(512) k_ln(int t, const float* __restrict__ gamma,
                                            const float* __restrict__ beta,
                                            float* __restrict__ out) {
    __shared__ float col[Hh];
    __shared__ float s1[16], s2[16];
    int b = blockIdx.x;
    int tid = threadIdx.x;
    float sum = 0.f, sq = 0.f;
    for (int r = tid; r < Hh; r += 512) {
        float v = g_hact[r * Bb + b];
        col[r] = v;
        sum += v;
        sq += v * v;
    }
    #pragma unroll
    for (int o = 16; o > 0; o >>= 1) {
        sum += __shfl_down_sync(0xffffffffu, sum, o);
        sq  += __shfl_down_sync(0xffffffffu, sq, o);
    }
    int w = tid >> 5, l = tid & 31;
    if (l == 0) { s1[w] = sum; s2[w] = sq; }
    __syncthreads();
    if (w == 0) {
        sum = (l < 16) ? s1[l] : 0.f;
        sq  = (l < 16) ? s2[l] : 0.f;
        #pragma unroll
        for (int o = 8; o > 0; o >>= 1) {
            sum += __shfl_down_sync(0xffffffffu, sum, o);
            sq  += __shfl_down_sync(0xffffffffu, sq, o);
        }
        if (l == 0) { s1[0] = sum; s2[0] = sq; }
    }
    __syncthreads();
    float mu = s1[0] * (1.0f / Hh);
    float var = s2[0] * (1.0f / Hh) - mu * mu;
    float rs = rsqrtf(var + 1e-5f);
    for (int r = tid; r < Hh; r += 512) {
        float hn = (col[r] - mu) * rs * gamma[r] + beta[r];
        g_h[r * Bb + b] = hn;
        out[((size_t)b * Tt + t) * Hh + r] = hn;
    }
}

__global__ void k_hlast(float* __restrict__ out) {
    int i = blockIdx.x * blockDim.x + threadIdx.x;   // over B*H
    if (i < Bb * Hh) {
        int b = i / Hh, r = i % Hh;
        out[(size_t)Bb * Tt * Hh + i] = g_h[r * Bb + b];
    }
}

// ---------------- launch ----------------

extern "C" void kernel_launch(void* const* d_in, const int* in_sizes, int n_in,
                              void* d_out, int out_size) {
    const float* x       = (const float*)d_in[0];
    const int*   ih_rows = (const int*)d_in[1];
    const int*   ih_cols = (const int*)d_in[2];
    const float* ih_vals = (const float*)d_in[3];
    const int*   hh_rows = (const int*)d_in[4];
    const int*   hh_cols = (const int*)d_in[5];
    const float* hh_vals = (const float*)d_in[6];
    const float* b_ih    = (const float*)d_in[7];
    const float* b_hh    = (const float*)d_in[8];
    const float* gamma   = (const float*)d_in[9];
    const float* beta    = (const float*)d_in[10];
    float* out = (float*)d_out;

    const int SMEM_WIN = WINC * Bb * 4;   // 131072
    static int attr_done = 0;
    cudaFuncSetAttribute(k_hh, cudaFuncAttributeMaxDynamicSharedMemorySize, SMEM_WIN);
    cudaFuncSetAttribute(k_ih, cudaFuncAttributeMaxDynamicSharedMemorySize, SMEM_WIN);
    (void)attr_done;

    // ---- bucket build ----
    k_zero_all<<<1024, 256>>>();
    k_zero_pairs<<<1024, 256>>>();
    k_hist<<<2048, 256>>>(hh_rows, hh_cols, NNZ_HH, 0);
    k_hist<<<1024, 256>>>(ih_rows, ih_cols, NNZ_IH, 1);
    k_scan_p1<<<32, 1024>>>(0, NK_HH);
    k_scan_p2<<<1, 32>>>(32);
    k_scan_p3<<<32, 1024>>>(0, NK_HH, 32);
    k_scan_p1<<<8, 1024>>>(1, NK_IH);
    k_scan_p2<<<1, 32>>>(8);
    k_scan_p3<<<8, 1024>>>(1, NK_IH, 8);
    k_scatter<<<2048, 256>>>(hh_rows, hh_cols, hh_vals, NNZ_HH, 0);
    k_scatter<<<1024, 256>>>(ih_rows, ih_cols, ih_vals, NNZ_IH, 1);

    // ---- x transpose + windowed ih precompute over all t ----
    k_transpose<<<dim3(Ii / 32, Tt), dim3(32, 8)>>>(x);
    k_ih<<<dim3(NC, Tt), 1024, SMEM_WIN>>>();

    // ---- recurrence ----
    for (int t = 0; t < Tt; t++) {
        k_hh<<<dim3(NC, NW_HH), 1024, SMEM_WIN>>>();
        k_reduce<<<HB / 1024, 1024>>>(t, b_ih, b_hh);
        k_ln<<<64, 512>>>(t, gamma, beta, out);
    }

    k_hlast<<<1024, 256>>>(out);
}

// round 6
// speedup vs baseline: 1.0071x; 1.0071x over previous
#include <cuda_runtime.h>
#include <math.h>

#define Bb 64
#define Tt 128
#define Ii 1024
#define Hh 4096
#define NNZ_IH 262144
#define NNZ_HH 1048576
#define HB (Hh * Bb)

#define NW_HH 8              // col windows of 512 for hh
#define NW_IH 2              // col windows of 512 for ih
#define WINC 512
#define NK_HH (NW_HH * Hh)   // 32768
#define NK_IH (NW_IH * Hh)   // 8192
#define PAD_HH (NNZ_HH + 8 * NK_HH)   // 1310720
#define PAD_IH (NNZ_IH + 8 * NK_IH)   // 327680
#define NC 16                // row chunks of 256
#define NBLK 128             // persistent grid (NC x NW_HH)

// ---------------- device scratch ----------------
__device__ __align__(16) float g_xT[Tt * Ii * Bb];     // (T, I, B)
__device__ __align__(16) float g_ihb[Tt * Hh * Bb];    // ih preact per t
__device__ __align__(16) float g_h[HB];                // hidden (H, B)
__device__ __align__(16) float g_hact[HB];             // tanh(pre)
__device__ __align__(16) float g_part[NW_HH * HB];     // hh window partials

__device__ __align__(16) int  g_hh_bptr[NK_HH + 4];
__device__ __align__(16) int  g_hh_bcnt[NK_HH];
__device__ __align__(16) int2 g_hh_pair[PAD_HH];
__device__ __align__(16) int  g_ih_bptr[NK_IH + 4];
__device__ __align__(16) int  g_ih_bcnt[NK_IH];
__device__ __align__(16) int2 g_ih_pair[PAD_IH];

__device__ int g_arrive;
__device__ volatile int g_release;

// ---------------- prep: init (zero + transpose) ----------------
// grid: 4096 transpose tile-blocks + 512 zero blocks, 256 threads
__global__ void k_init(const float* __restrict__ x) {
    int bid = blockIdx.x;
    if (bid < 4096) {
        __shared__ float tile[32][Bb + 1];
        int i0 = (bid & 31) * 32;
        int t = bid >> 5;
        int tx = threadIdx.x & 31, ty = threadIdx.x >> 5;   // 32 x 8
        #pragma unroll
        for (int bq = 0; bq < 8; bq++) {
            int b = ty + 8 * bq;
            tile[tx][b] = x[((size_t)b * Tt + t) * Ii + i0 + tx];
        }
        __syncthreads();
        #pragma unroll
        for (int k = 0; k < 8; k++) {
            int idx = threadIdx.x + 256 * k;
            int iy = idx >> 6;
            int b = idx & 63;
            g_xT[((size_t)t * Ii + i0 + iy) * Bb + b] = tile[iy][b];
        }
    } else {
        int zb = bid - 4096;                    // 0..511
        int tid = zb * 256 + threadIdx.x;       // 131072 threads
        int4 z4; z4.x = z4.y = z4.z = z4.w = 0;
        // pairs: (PAD_HH + PAD_IH)/2 int4 = 819200
        for (int i = tid; i < PAD_HH / 2; i += 131072) ((int4*)g_hh_pair)[i] = z4;
        for (int i = tid; i < PAD_IH / 2; i += 131072) ((int4*)g_ih_pair)[i] = z4;
        // h
        float4 zf; zf.x = zf.y = zf.z = zf.w = 0.f;
        for (int i = tid; i < HB / 4; i += 131072) ((float4*)g_h)[i] = zf;
        // counts
        for (int i = tid; i < NK_HH; i += 131072) g_hh_bcnt[i] = 0;
        for (int i = tid; i < NK_IH; i += 131072) g_ih_bcnt[i] = 0;
        if (tid == 0) { g_arrive = 0; g_release = 0; }
    }
}

// ---------------- prep: fused histogram ----------------
__global__ void k_hist(const int* __restrict__ hr, const int* __restrict__ hc,
                       const int* __restrict__ ir, const int* __restrict__ ic) {
    for (int i = blockIdx.x * blockDim.x + threadIdx.x; i < NNZ_HH + NNZ_IH;
         i += gridDim.x * blockDim.x) {
        if (i < NNZ_HH) atomicAdd(&g_hh_bcnt[(hc[i] >> 9) * Hh + hr[i]], 1);
        else {
            int j = i - NNZ_HH;
            atomicAdd(&g_ih_bcnt[(ic[j] >> 9) * Hh + ir[j]], 1);
        }
    }
}

// ---------------- prep: scan (2 blocks: 0=hh, 1=ih) ----------------
__global__ void __launch_bounds__(1024) k_scan() {
    int which = blockIdx.x;
    int n = which ? NK_IH : NK_HH;
    int* cnt = which ? g_ih_bcnt : g_hh_bcnt;
    int* ptr = which ? g_ih_bptr : g_hh_bptr;
    __shared__ int wsum[32];
    __shared__ int carry;
    int tid = threadIdx.x, lane = tid & 31, wid = tid >> 5;
    if (tid == 0) carry = 0;
    __syncthreads();
    int ntiles = n >> 10;
    for (int tile = 0; tile < ntiles; tile++) {
        int i = (tile << 10) + tid;
        int v = (cnt[i] + 7) & ~7;
        int incl = v;
        #pragma unroll
        for (int o = 1; o < 32; o <<= 1) {
            int u = __shfl_up_sync(0xffffffffu, incl, o);
            if (lane >= o) incl += u;
        }
        if (lane == 31) wsum[wid] = incl;
        __syncthreads();
        if (wid == 0) {
            int s = wsum[lane];
            int si = s;
            #pragma unroll
            for (int o = 1; o < 32; o <<= 1) {
                int u = __shfl_up_sync(0xffffffffu, si, o);
                if (lane >= o) si += u;
            }
            wsum[lane] = si - s;
        }
        __syncthreads();
        int excl = incl - v + wsum[wid] + carry;
        ptr[i] = excl;
        cnt[i] = excl;                // scatter cursor
        __syncthreads();
        if (tid == 1023) carry = excl + v;
        __syncthreads();
    }
    if (tid == 1023) ptr[n] = carry;
}

// ---------------- prep: fused scatter ----------------
__global__ void k_scatter(const int* __restrict__ hr, const int* __restrict__ hc,
                          const float* __restrict__ hv,
                          const int* __restrict__ ir, const int* __restrict__ ic,
                          const float* __restrict__ iv) {
    for (int i = blockIdx.x * blockDim.x + threadIdx.x; i < NNZ_HH + NNZ_IH;
         i += gridDim.x * blockDim.x) {
        if (i < NNZ_HH) {
            int c = hc[i];
            int p = atomicAdd(&g_hh_bcnt[(c >> 9) * Hh + hr[i]], 1);
            int2 pr; pr.x = (c & (WINC - 1)) << 8; pr.y = __float_as_int(hv[i]);
            g_hh_pair[p] = pr;
        } else {
            int j = i - NNZ_HH;
            int c = ic[j];
            int p = atomicAdd(&g_ih_bcnt[(c >> 9) * Hh + ir[j]], 1);
            int2 pr; pr.x = (c & (WINC - 1)) << 8; pr.y = __float_as_int(iv[j]);
            g_ih_pair[p] = pr;
        }
    }
}

// ---------------- gather core ----------------
__device__ __forceinline__ void bucket8(const int2* __restrict__ pair, int s, int e,
                                        const char* shb, int lane8,
                                        float& ax, float& ay) {
    for (int base = s; base < e; base += 8) {
        int2 q[8];
        #pragma unroll
        for (int j = 0; j < 8; j++) q[j] = __ldg(&pair[base + j]);
        #pragma unroll
        for (int j = 0; j < 8; j++) {
            float2 hv = *(const float2*)(shb + q[j].x + lane8);
            float v = __int_as_float(q[j].y);
            ax = fmaf(v, hv.x, ax);
            ay = fmaf(v, hv.y, ay);
        }
    }
}

// ---------------- prep: windowed ih precompute over all t ----------------
__global__ void __launch_bounds__(1024, 1) k_ih() {
    extern __shared__ float sh[];
    int t = blockIdx.y;
    int chunk0 = blockIdx.x * 256;
    int tid = threadIdx.x;
    int lane = tid & 31, warp = tid >> 5;
    int lane8 = lane << 3;
    const char* shb = (const char*)sh;
    float2 acc[8];
    #pragma unroll
    for (int k = 0; k < 8; k++) { acc[k].x = 0.f; acc[k].y = 0.f; }
    for (int w = 0; w < NW_IH; w++) {
        __syncthreads();
        const float4* src = (const float4*)(g_xT + (size_t)t * Ii * Bb + w * WINC * Bb);
        float4* dst = (float4*)sh;
        #pragma unroll
        for (int i = tid; i < WINC * Bb / 4; i += 1024) dst[i] = src[i];
        __syncthreads();
        #pragma unroll
        for (int k = 0; k < 8; k++) {
            int r = chunk0 + warp + 32 * k;
            bucket8(g_ih_pair, g_ih_bptr[w * Hh + r], g_ih_bptr[w * Hh + r + 1],
                    shb, lane8, acc[k].x, acc[k].y);
        }
    }
    float* ob = g_ihb + (size_t)t * HB;
    #pragma unroll
    for (int k = 0; k < 8; k++) {
        int r = chunk0 + warp + 32 * k;
        ((float2*)(ob + r * Bb))[lane] = acc[k];
    }
}

// ---------------- persistent recurrence kernel ----------------
__device__ __forceinline__ void gbar(int& epoch) {
    epoch++;
    __syncthreads();
    if (threadIdx.x == 0) {
        __threadfence();
        int v = atomicAdd(&g_arrive, 1);
        if (v == NBLK * epoch - 1) {
            g_release = epoch;
        } else {
            while (g_release < epoch) __nanosleep(64);
        }
        __threadfence();
    }
    __syncthreads();
}

__global__ void __launch_bounds__(1024, 1) k_persist(const float* __restrict__ b_ih,
                                                     const float* __restrict__ b_hh,
                                                     const float* __restrict__ gamma,
                                                     const float* __restrict__ beta,
                                                     float* __restrict__ out) {
    extern __shared__ float sh[];
    int bid = blockIdx.x;                // 0..127
    int w = bid >> 4;                    // window 0..7
    int chunk0 = (bid & 15) * 256;       // row chunk
    int tid = threadIdx.x;
    int lane = tid & 31, warp = tid >> 5;
    int lane8 = lane << 3;
    const char* shb = (const char*)sh;
    int epoch = 0;

    // cache bucket ranges for this block's 256 rows (8 per warp)
    int bs[8], be[8];
    #pragma unroll
    for (int k = 0; k < 8; k++) {
        int r = chunk0 + warp + 32 * k;
        bs[k] = g_hh_bptr[w * Hh + r];
        be[k] = g_hh_bptr[w * Hh + r + 1];
    }

    for (int t = 0; t < Tt; t++) {
        // ---- phase A: stage h window, gather, write partials ----
        {
            const float4* src = (const float4*)(g_h + w * WINC * Bb);
            float4* dst = (float4*)sh;
            #pragma unroll
            for (int i = tid; i < WINC * Bb / 4; i += 1024) dst[i] = src[i];
        }
        __syncthreads();
        #pragma unroll
        for (int k = 0; k < 8; k++) {
            int r = chunk0 + warp + 32 * k;
            float ax = 0.f, ay = 0.f;
            bucket8(g_hh_pair, bs[k], be[k], shb, lane8, ax, ay);
            float2 o; o.x = ax; o.y = ay;
            ((float2*)(g_part + (size_t)(w * Hh + r) * Bb))[lane] = o;
        }
        __syncthreads();     // sh reuse safety before next use
        gbar(epoch);

        // ---- phase B: reduce windows + bias + tanh ----
        {
            int i2 = bid * 1024 + tid;            // float2 index over HB/2
            int r = i2 >> 5;
            const float2* ihb2 = (const float2*)(g_ihb + (size_t)t * HB);
            float2 v = ihb2[i2];
            float bias = __ldg(&b_ih[r]) + __ldg(&b_hh[r]);
            float ax = bias + v.x, ay = bias + v.y;
            #pragma unroll
            for (int ww = 0; ww < NW_HH; ww++) {
                float2 p = ((const float2*)g_part)[(size_t)ww * (HB / 2) + i2];
                ax += p.x; ay += p.y;
            }
            float2 o; o.x = tanhf(ax); o.y = tanhf(ay);
            ((float2*)g_hact)[i2] = o;
        }
        gbar(epoch);

        // ---- phase C: layernorm per batch column (blocks 0..63) ----
        if (bid < Bb) {
            int b = bid;
            float* col = sh;                       // 4096 floats
            __shared__ float s1[32], s2[32];
            float sum = 0.f, sq = 0.f;
            for (int r = tid; r < Hh; r += 1024) {
                float v = g_hact[r * Bb + b];
                col[r] = v;
                sum += v; sq += v * v;
            }
            #pragma unroll
            for (int o = 16; o > 0; o >>= 1) {
                sum += __shfl_down_sync(0xffffffffu, sum, o);
                sq  += __shfl_down_sync(0xffffffffu, sq, o);
            }
            if (lane == 0) { s1[warp] = sum; s2[warp] = sq; }
            __syncthreads();
            if (warp == 0) {
                sum = s1[lane]; sq = s2[lane];
                #pragma unroll
                for (int o = 16; o > 0; o >>= 1) {
                    sum += __shfl_down_sync(0xffffffffu, sum, o);
                    sq  += __shfl_down_sync(0xffffffffu, sq, o);
                }
                if (lane == 0) { s1[0] = sum; s2[0] = sq; }
            }
            __syncthreads();
            float mu = s1[0] * (1.0f / Hh);
            float var = s2[0] * (1.0f / Hh) - mu * mu;
            float rs = rsqrtf(var + 1e-5f);
            for (int r = tid; r < Hh; r += 1024) {
                float hn = (col[r] - mu) * rs * __ldg(&gamma[r]) + __ldg(&beta[r]);
                g_h[r * Bb + b] = hn;
                out[((size_t)b * Tt + t) * Hh + r] = hn;
                if (t == Tt - 1)
                    out[(size_t)Bb * Tt * Hh + (size_t)b * Hh + r] = hn;
            }
            __syncthreads();
        }
        gbar(epoch);
    }
}

// ---------------- launch ----------------
extern "C" void kernel_launch(void* const* d_in, const int* in_sizes, int n_in,
                              void* d_out, int out_size) {
    const float* x       = (const float*)d_in[0];
    const int*   ih_rows = (const int*)d_in[1];
    const int*   ih_cols = (const int*)d_in[2];
    const float* ih_vals = (const float*)d_in[3];
    const int*   hh_rows = (const int*)d_in[4];
    const int*   hh_cols = (const int*)d_in[5];
    const float* hh_vals = (const float*)d_in[6];
    const float* b_ih    = (const float*)d_in[7];
    const float* b_hh    = (const float*)d_in[8];
    const float* gamma   = (const float*)d_in[9];
    const float* beta    = (const float*)d_in[10];
    float* out = (float*)d_out;

    const int SMEM_WIN = WINC * Bb * 4;   // 131072
    cudaFuncSetAttribute(k_ih, cudaFuncAttributeMaxDynamicSharedMemorySize, SMEM_WIN);
    cudaFuncSetAttribute(k_persist, cudaFuncAttributeMaxDynamicSharedMemorySize, SMEM_WIN);

    // 5 prep launches, then the persistent kernel (launch #6)
    k_init<<<4096 + 512, 256>>>(x);
    k_hist<<<2048, 256>>>(hh_rows, hh_cols, ih_rows, ih_cols);
    k_scan<<<2, 1024>>>();
    k_scatter<<<2048, 256>>>(hh_rows, hh_cols, hh_vals, ih_rows, ih_cols, ih_vals);
    k_ih<<<dim3(NC, Tt), 1024, SMEM_WIN>>>();
    k_persist<<<NBLK, 1024, SMEM_WIN>>>(b_ih, b_hh, gamma, beta, out);
}

// round 8
// speedup vs baseline: 1.0089x; 1.0018x over previous
#include <cuda_runtime.h>
#include <math.h>

#define Bb 64
#define Tt 128
#define Ii 1024
#define Hh 4096
#define NNZ_IH 262144
#define NNZ_HH 1048576
#define HB (Hh * Bb)

#define NW_HH 8              // col windows of 512 for hh
#define NW_IH 2              // col windows of 512 for ih
#define WINC 512
#define NK_HH (NW_HH * Hh)   // 32768
#define NK_IH (NW_IH * Hh)   // 8192
#define PAD_HH (NNZ_HH + 8 * NK_HH)   // 1310720
#define PAD_IH (NNZ_IH + 8 * NK_IH)   // 327680
#define NC 16                // row chunks of 256
#define NBLK 128             // persistent grid
#define TSTR 66              // smem transpose row stride (floats); 66*4=264 % 8 == 0

// ---------------- device scratch ----------------
__device__ __align__(16) float g_xT[Tt * Ii * Bb];     // (T, I, B)
__device__ __align__(16) float g_ihb[Tt * Hh * Bb];    // ih preact per t (H,B)
__device__ __align__(16) float g_h[HB];                // hidden (H, B)
__device__ __align__(16) float g_hactT[Bb * Hh];       // tanh(pre), (B, H)
__device__ __align__(16) float g_part[NW_HH * HB];     // hh window partials

__device__ __align__(16) int  g_hh_bptr[NK_HH + 4];
__device__ __align__(16) int  g_hh_bcnt[NK_HH];
__device__ __align__(16) int2 g_hh_pair[PAD_HH];
__device__ __align__(16) int  g_ih_bptr[NK_IH + 4];
__device__ __align__(16) int  g_ih_bcnt[NK_IH];
__device__ __align__(16) int2 g_ih_pair[PAD_IH];

__device__ int g_flags[NBLK];
__device__ volatile int g_release;

// ---------------- prep: init (zero + transpose) ----------------
__global__ void k_init(const float* __restrict__ x) {
    int bid = blockIdx.x;
    if (bid < 4096) {
        __shared__ float tile[32][Bb + 1];
        int i0 = (bid & 31) * 32;
        int t = bid >> 5;
        int tx = threadIdx.x & 31, ty = threadIdx.x >> 5;   // 32 x 8
        #pragma unroll
        for (int bq = 0; bq < 8; bq++) {
            int b = ty + 8 * bq;
            tile[tx][b] = x[((size_t)b * Tt + t) * Ii + i0 + tx];
        }
        __syncthreads();
        #pragma unroll
        for (int k = 0; k < 8; k++) {
            int idx = threadIdx.x + 256 * k;
            int iy = idx >> 6;
            int b = idx & 63;
            g_xT[((size_t)t * Ii + i0 + iy) * Bb + b] = tile[iy][b];
        }
    } else {
        int zb = bid - 4096;                    // 0..511
        int tid = zb * 256 + threadIdx.x;       // 131072 threads
        int4 z4; z4.x = z4.y = z4.z = z4.w = 0;
        for (int i = tid; i < PAD_HH / 2; i += 131072) ((int4*)g_hh_pair)[i] = z4;
        for (int i = tid; i < PAD_IH / 2; i += 131072) ((int4*)g_ih_pair)[i] = z4;
        float4 zf; zf.x = zf.y = zf.z = zf.w = 0.f;
        for (int i = tid; i < HB / 4; i += 131072) ((float4*)g_h)[i] = zf;
        for (int i = tid; i < NK_HH; i += 131072) g_hh_bcnt[i] = 0;
        for (int i = tid; i < NK_IH; i += 131072) g_ih_bcnt[i] = 0;
        if (tid < NBLK) g_flags[tid] = 0;
        if (tid == 0) g_release = 0;
    }
}

// ---------------- prep: fused histogram ----------------
__global__ void k_hist(const int* __restrict__ hr, const int* __restrict__ hc,
                       const int* __restrict__ ir, const int* __restrict__ ic) {
    for (int i = blockIdx.x * blockDim.x + threadIdx.x; i < NNZ_HH + NNZ_IH;
         i += gridDim.x * blockDim.x) {
        if (i < NNZ_HH) atomicAdd(&g_hh_bcnt[(hc[i] >> 9) * Hh + hr[i]], 1);
        else {
            int j = i - NNZ_HH;
            atomicAdd(&g_ih_bcnt[(ic[j] >> 9) * Hh + ir[j]], 1);
        }
    }
}

// ---------------- prep: scan (2 blocks: 0=hh, 1=ih) ----------------
__global__ void __launch_bounds__(1024) k_scan() {
    int which = blockIdx.x;
    int n = which ? NK_IH : NK_HH;
    int* cnt = which ? g_ih_bcnt : g_hh_bcnt;
    int* ptr = which ? g_ih_bptr : g_hh_bptr;
    __shared__ int wsum[32];
    __shared__ int carry;
    int tid = threadIdx.x, lane = tid & 31, wid = tid >> 5;
    if (tid == 0) carry = 0;
    __syncthreads();
    int ntiles = n >> 10;
    for (int tile = 0; tile < ntiles; tile++) {
        int i = (tile << 10) + tid;
        int v = (cnt[i] + 7) & ~7;
        int incl = v;
        #pragma unroll
        for (int o = 1; o < 32; o <<= 1) {
            int u = __shfl_up_sync(0xffffffffu, incl, o);
            if (lane >= o) incl += u;
        }
        if (lane == 31) wsum[wid] = incl;
        __syncthreads();
        if (wid == 0) {
            int s = wsum[lane];
            int si = s;
            #pragma unroll
            for (int o = 1; o < 32; o <<= 1) {
                int u = __shfl_up_sync(0xffffffffu, si, o);
                if (lane >= o) si += u;
            }
            wsum[lane] = si - s;
        }
        __syncthreads();
        int excl = incl - v + wsum[wid] + carry;
        ptr[i] = excl;
        cnt[i] = excl;
        __syncthreads();
        if (tid == 1023) carry = excl + v;
        __syncthreads();
    }
    if (tid == 1023) ptr[n] = carry;
}

// ---------------- prep: fused scatter ----------------
__global__ void k_scatter(const int* __restrict__ hr, const int* __restrict__ hc,
                          const float* __restrict__ hv,
                          const int* __restrict__ ir, const int* __restrict__ ic,
                          const float* __restrict__ iv) {
    for (int i = blockIdx.x * blockDim.x + threadIdx.x; i < NNZ_HH + NNZ_IH;
         i += gridDim.x * blockDim.x) {
        if (i < NNZ_HH) {
            int c = hc[i];
            int p = atomicAdd(&g_hh_bcnt[(c >> 9) * Hh + hr[i]], 1);
            int2 pr; pr.x = (c & (WINC - 1)) << 8; pr.y = __float_as_int(hv[i]);
            g_hh_pair[p] = pr;
        } else {
            int j = i - NNZ_HH;
            int c = ic[j];
            int p = atomicAdd(&g_ih_bcnt[(c >> 9) * Hh + ir[j]], 1);
            int2 pr; pr.x = (c & (WINC - 1)) << 8; pr.y = __float_as_int(iv[j]);
            g_ih_pair[p] = pr;
        }
    }
}

// ---------------- pipelined gather core (padded buckets of 8 = 4 int4) ----------------
__device__ __forceinline__ void proc4(int4 c, const char* shb, int lane8,
                                      float& ax, float& ay) {
    float2 h0 = *(const float2*)(shb + c.x + lane8);
    float v0 = __int_as_float(c.y);
    ax = fmaf(v0, h0.x, ax);
    ay = fmaf(v0, h0.y, ay);
    float2 h1 = *(const float2*)(shb + c.z + lane8);
    float v1 = __int_as_float(c.w);
    ax = fmaf(v1, h1.x, ax);
    ay = fmaf(v1, h1.y, ay);
}

__device__ __forceinline__ void bucket8p(const int4* __restrict__ p4, int s, int e,
                                         const char* shb, int lane8,
                                         float& ax, float& ay) {
    int i4 = s >> 1, e4 = e >> 1;
    int4 n0, n1, n2, n3;
    if (i4 < e4) {
        n0 = __ldg(p4 + i4);     n1 = __ldg(p4 + i4 + 1);
        n2 = __ldg(p4 + i4 + 2); n3 = __ldg(p4 + i4 + 3);
    }
    for (; i4 < e4; i4 += 4) {
        int4 c0 = n0, c1 = n1, c2 = n2, c3 = n3;
        if (i4 + 4 < e4) {
            n0 = __ldg(p4 + i4 + 4); n1 = __ldg(p4 + i4 + 5);
            n2 = __ldg(p4 + i4 + 6); n3 = __ldg(p4 + i4 + 7);
        }
        proc4(c0, shb, lane8, ax, ay);
        proc4(c1, shb, lane8, ax, ay);
        proc4(c2, shb, lane8, ax, ay);
        proc4(c3, shb, lane8, ax, ay);
    }
}

// ---------------- prep: windowed ih precompute over all t ----------------
__global__ void __launch_bounds__(1024, 1) k_ih() {
    extern __shared__ float sh[];
    int t = blockIdx.y;
    int chunk0 = blockIdx.x * 256;
    int tid = threadIdx.x;
    int lane = tid & 31, warp = tid >> 5;
    int lane8 = lane << 3;
    const char* shb = (const char*)sh;
    float2 acc[8];
    #pragma unroll
    for (int k = 0; k < 8; k++) { acc[k].x = 0.f; acc[k].y = 0.f; }
    for (int w = 0; w < NW_IH; w++) {
        __syncthreads();
        const float4* src = (const float4*)(g_xT + (size_t)t * Ii * Bb + w * WINC * Bb);
        float4* dst = (float4*)sh;
        #pragma unroll
        for (int i = tid; i < WINC * Bb / 4; i += 1024) dst[i] = src[i];
        __syncthreads();
        #pragma unroll
        for (int k = 0; k < 8; k++) {
            int r = chunk0 + warp + 32 * k;
            bucket8p((const int4*)g_ih_pair, g_ih_bptr[w * Hh + r],
                     g_ih_bptr[w * Hh + r + 1], shb, lane8, acc[k].x, acc[k].y);
        }
    }
    float* ob = g_ihb + (size_t)t * HB;
    #pragma unroll
    for (int k = 0; k < 8; k++) {
        int r = chunk0 + warp + 32 * k;
        ((float2*)(ob + r * Bb))[lane] = acc[k];
    }
}

// ---------------- flag-array global barrier ----------------
__device__ __forceinline__ void gbar(int& epoch, int bid, int tid) {
    epoch++;
    __syncthreads();
    if (tid == 0) {
        __threadfence();
        ((volatile int*)g_flags)[bid] = epoch;
    }
    if (bid == 0) {
        if (tid < NBLK) {
            while (((volatile int*)g_flags)[tid] < epoch) __nanosleep(32);
        }
        __syncthreads();
        if (tid == 0) {
            __threadfence();
            g_release = epoch;
        }
    }
    if (tid == 0) {
        while (g_release < epoch) __nanosleep(32);
        __threadfence();
    }
    __syncthreads();
}

// ---------------- persistent recurrence kernel ----------------
__global__ void __launch_bounds__(1024, 1) k_persist(const float* __restrict__ b_ih,
                                                     const float* __restrict__ b_hh,
                                                     const float* __restrict__ gamma,
                                                     const float* __restrict__ beta,
                                                     float* __restrict__ out) {
    extern __shared__ float sh[];
    int bid = blockIdx.x;                // 0..127
    int w = bid >> 4;                    // window 0..7
    int chunk0 = (bid & 15) * 256;       // row chunk
    int tid = threadIdx.x;
    int lane = tid & 31, warp = tid >> 5;
    int lane8 = lane << 3;
    const char* shb = (const char*)sh;
    int epoch = 0;

    int bs[8], be[8];
    #pragma unroll
    for (int k = 0; k < 8; k++) {
        int r = chunk0 + warp + 32 * k;
        bs[k] = g_hh_bptr[w * Hh + r];
        be[k] = g_hh_bptr[w * Hh + r + 1];
    }

    for (int t = 0; t < Tt; t++) {
        // ---- phase A: stage h window, pipelined gather, write partials ----
        {
            const float4* src = (const float4*)(g_h + w * WINC * Bb);
            float4* dst = (float4*)sh;
            #pragma unroll
            for (int i = tid; i < WINC * Bb / 4; i += 1024) dst[i] = src[i];
        }
        __syncthreads();
        #pragma unroll
        for (int k = 0; k < 8; k++) {
            int r = chunk0 + warp + 32 * k;
            float ax = 0.f, ay = 0.f;
            bucket8p((const int4*)g_hh_pair, bs[k], be[k], shb, lane8, ax, ay);
            float2 o; o.x = ax; o.y = ay;
            ((float2*)(g_part + (size_t)(w * Hh + r) * Bb))[lane] = o;
        }
        __syncthreads();
        gbar(epoch, bid, tid);

        // ---- phase B: reduce windows + bias + tanh -> hactT (B,H) ----
        {
            int i2 = bid * 1024 + tid;            // float2 index over HB/2
            int r = i2 >> 5;                      // hidden row
            const float2* ihb2 = (const float2*)(g_ihb + (size_t)t * HB);
            float2 v = ihb2[i2];
            float bias = __ldg(&b_ih[r]) + __ldg(&b_hh[r]);
            float ax = bias + v.x, ay = bias + v.y;
            #pragma unroll
            for (int ww = 0; ww < NW_HH; ww++) {
                float2 p = ((const float2*)g_part)[(size_t)ww * (HB / 2) + i2];
                ax += p.x; ay += p.y;
            }
            // transpose 32x64 tile in smem (row stride TSTR=66 floats, 8B aligned)
            int rl = tid >> 5;                    // local row 0..31
            float2 o; o.x = tanhf(ax); o.y = tanhf(ay);
            *(float2*)(sh + rl * TSTR + (tid & 31) * 2) = o;
        }
        __syncthreads();
        if (tid < 512) {
            int b = tid >> 3;                     // 0..63
            int f4 = tid & 7;                     // 0..7 (float4 group of rows)
            float4 o;
            o.x = sh[(f4 * 4 + 0) * TSTR + b];
            o.y = sh[(f4 * 4 + 1) * TSTR + b];
            o.z = sh[(f4 * 4 + 2) * TSTR + b];
            o.w = sh[(f4 * 4 + 3) * TSTR + b];
            *(float4*)(g_hactT + (size_t)b * Hh + bid * 32 + f4 * 4) = o;
        }
        __syncthreads();
        gbar(epoch, bid, tid);

        // ---- phase C: layernorm per batch column (blocks 0..63), coalesced ----
        if (bid < Bb) {
            int b = bid;
            __shared__ float s1[32], s2[32];
            const float4* src = (const float4*)(g_hactT + (size_t)b * Hh);
            float4 v = src[tid];                 // rows 4*tid .. 4*tid+3
            float sum = v.x + v.y + v.z + v.w;
            float sq = v.x * v.x + v.y * v.y + v.z * v.z + v.w * v.w;
            #pragma unroll
            for (int o = 16; o > 0; o >>= 1) {
                sum += __shfl_down_sync(0xffffffffu, sum, o);
                sq  += __shfl_down_sync(0xffffffffu, sq, o);
            }
            if (lane == 0) { s1[warp] = sum; s2[warp] = sq; }
            __syncthreads();
            if (warp == 0) {
                sum = s1[lane]; sq = s2[lane];
                #pragma unroll
                for (int o = 16; o > 0; o >>= 1) {
                    sum += __shfl_down_sync(0xffffffffu, sum, o);
                    sq  += __shfl_down_sync(0xffffffffu, sq, o);
                }
                if (lane == 0) { s1[0] = sum; s2[0] = sq; }
            }
            __syncthreads();
            float mu = s1[0] * (1.0f / Hh);
            float var = s2[0] * (1.0f / Hh) - mu * mu;
            float rs = rsqrtf(var + 1e-5f);
            int r4 = tid * 4;
            float4 g = ((const float4*)gamma)[tid];
            float4 be4 = ((const float4*)beta)[tid];
            float4 hn;
            hn.x = (v.x - mu) * rs * g.x + be4.x;
            hn.y = (v.y - mu) * rs * g.y + be4.y;
            hn.z = (v.z - mu) * rs * g.z + be4.z;
            hn.w = (v.w - mu) * rs * g.w + be4.w;
            *(float4*)(out + ((size_t)b * Tt + t) * Hh + r4) = hn;
            g_h[(r4 + 0) * Bb + b] = hn.x;
            g_h[(r4 + 1) * Bb + b] = hn.y;
            g_h[(r4 + 2) * Bb + b] = hn.z;
            g_h[(r4 + 3) * Bb + b] = hn.w;
            if (t == Tt - 1)
                *(float4*)(out + (size_t)Bb * Tt * Hh + (size_t)b * Hh + r4) = hn;
            __syncthreads();
        }
        gbar(epoch, bid, tid);
    }
}

// ---------------- launch ----------------
extern "C" void kernel_launch(void* const* d_in, const int* in_sizes, int n_in,
                              void* d_out, int out_size) {
    const float* x       = (const float*)d_in[0];
    const int*   ih_rows = (const int*)d_in[1];
    const int*   ih_cols = (const int*)d_in[2];
    const float* ih_vals = (const float*)d_in[3];
    const int*   hh_rows = (const int*)d_in[4];
    const int*   hh_cols = (const int*)d_in[5];
    const float* hh_vals = (const float*)d_in[6];
    const float* b_ih    = (const float*)d_in[7];
    const float* b_hh    = (const float*)d_in[8];
    const float* gamma   = (const float*)d_in[9];
    const float* beta    = (const float*)d_in[10];
    float* out = (float*)d_out;

    const int SMEM_WIN = WINC * Bb * 4;   // 131072
    cudaFuncSetAttribute(k_ih, cudaFuncAttributeMaxDynamicSharedMemorySize, SMEM_WIN);
    cudaFuncSetAttribute(k_persist, cudaFuncAttributeMaxDynamicSharedMemorySize, SMEM_WIN);

    // 5 prep launches, then the persistent kernel (launch #6)
    k_init<<<4096 + 512, 256>>>(x);
    k_hist<<<2048, 256>>>(hh_rows, hh_cols, ih_rows, ih_cols);
    k_scan<<<2, 1024>>>();
    k_scatter<<<2048, 256>>>(hh_rows, hh_cols, hh_vals, ih_rows, ih_cols, ih_vals);
    k_ih<<<dim3(NC, Tt), 1024, SMEM_WIN>>>();
    k_persist<<<NBLK, 1024, SMEM_WIN>>>(b_ih, b_hh, gamma, beta, out);
}